// round 11
// baseline (speedup 1.0000x reference)
#include <cuda_runtime.h>
#include <cuda_bf16.h>
#include <cstdint>

#define N_NODES 50000
#define N_EDGES 800000
#define D 128

#define BUILD_BLOCKS 148
#define BUILD_THREADS 1024

typedef unsigned int u32;

// ---------------------------------------------------------------------------
// Scratch (device globals: allocation-free per harness rules)
// ---------------------------------------------------------------------------
__device__ float4 g_hn4[(size_t)N_NODES * D / 4];  // h_neigh (mean), 25.6MB
__device__ int    g_cnt[N_NODES];                  // in-degree
__device__ int    g_off[N_NODES];                  // CSR offsets
__device__ int    g_cur[N_NODES];                  // fill cursors
__device__ int    g_esrc[N_EDGES];                 // src per edge, bucketed by dst
__device__ int    g_part[BUILD_BLOCKS];            // per-block scan partials
__device__ u32    g_barc;                          // grid barrier counter (self-reset)
__device__ int    g_stride;                        // 1 = int32 indices, 2 = int64

__device__ __forceinline__ u32 f2tf32(float f) {
    u32 r; asm("cvt.rna.tf32.f32 %0, %1;" : "=r"(r) : "f"(f)); return r;
}

// Grid barrier #n (1-based, cumulative). 148 CTAs <= 148 SMs -> co-resident.
__device__ __forceinline__ void grid_bar(int n) {
    __syncthreads();
    __threadfence();
    if (threadIdx.x == 0) {
        atomicAdd(&g_barc, 1u);
        u32 target = (u32)n * BUILD_BLOCKS;
        while (atomicAdd(&g_barc, 0u) < target) __nanosleep(64);
    }
    __syncthreads();
}

// ---------------------------------------------------------------------------
// K1: fused CSR build — zero+probe, count, scan, fill (one persistent kernel)
// ---------------------------------------------------------------------------
__global__ __launch_bounds__(BUILD_THREADS)
void build_kernel(const int* __restrict__ src_w, const int* __restrict__ dst_w) {
    const int tid  = threadIdx.x;
    const int b    = blockIdx.x;
    const int gtid = b * BUILD_THREADS + tid;
    const int gsz  = BUILD_BLOCKS * BUILD_THREADS;   // 151552

    __shared__ int ssum[BUILD_THREADS];

    // ---- phase 0: zero counters + probe index dtype (block 0) ----
    for (int i = gtid; i < N_NODES; i += gsz) { g_cnt[i] = 0; g_cur[i] = 0; }
    if (b == 0) {
        __shared__ int any_nonzero;
        if (tid == 0) any_nonzero = 0;
        __syncthreads();
        if (tid < 256) {
            int j = 1 + 2 * tid;             // odd 32-bit words: all 0 iff int64
            if ((dst_w[j] | dst_w[j + 512]) != 0) atomicOr(&any_nonzero, 1);
        }
        __syncthreads();
        if (tid == 0) g_stride = any_nonzero ? 1 : 2;
    }
    grid_bar(1);

    // ---- phase 1: degree histogram ----
    const int st = g_stride;
    for (int e = gtid; e < N_EDGES; e += gsz)
        atomicAdd(&g_cnt[dst_w[(size_t)e * st]], 1);
    grid_bar(2);

    // ---- phase 2a: per-thread sums + block inclusive scan (all threads) ----
    const int chunk = (N_NODES + BUILD_BLOCKS - 1) / BUILD_BLOCKS;      // 338
    const int lo = b * chunk;
    const int hi = (lo + chunk < N_NODES) ? lo + chunk : N_NODES;
    const int sub = (chunk + BUILD_THREADS - 1) / BUILD_THREADS;        // 1
    const int tlo = lo + tid * sub;
    const int thi = (tlo + sub < hi) ? tlo + sub : hi;

    int ts = 0;
    for (int i = tlo; i < thi; i++) ts += g_cnt[i];
    ssum[tid] = ts;
    __syncthreads();
    for (int o = 1; o < BUILD_THREADS; o <<= 1) {
        int x = (tid >= o) ? ssum[tid - o] : 0;
        __syncthreads();
        ssum[tid] += x;
        __syncthreads();
    }
    if (tid == 0) g_part[b] = ssum[BUILD_THREADS - 1];
    grid_bar(3);

    // ---- phase 2b: warp 0 of block 0 exclusive-scans the 148 block totals
    //      (single-warp shfl scan; legal under divergence, no __syncthreads) ----
    if (b == 0 && tid < 32) {
        int carry = 0;
#pragma unroll
        for (int c0 = 0; c0 < BUILD_BLOCKS; c0 += 32) {
            int i = c0 + tid;
            int v = (i < BUILD_BLOCKS) ? g_part[i] : 0;
            int x = v;
#pragma unroll
            for (int o = 1; o < 32; o <<= 1) {        // inclusive shfl scan
                int y = __shfl_up_sync(0xFFFFFFFFu, x, o);
                if (tid >= o) x += y;
            }
            if (i < BUILD_BLOCKS) g_part[i] = carry + x - v;   // exclusive
            carry += __shfl_sync(0xFFFFFFFFu, x, 31);          // chunk total
        }
    }
    grid_bar(4);

    // ---- phase 2c: write offsets ----
    {
        int base = g_part[b] + (tid > 0 ? ssum[tid - 1] : 0);
        for (int i = tlo; i < thi; i++) { g_off[i] = base; base += g_cnt[i]; }
    }
    grid_bar(5);

    // ---- phase 3: bucket fill ----
    for (int e = gtid; e < N_EDGES; e += gsz) {
        int d = dst_w[(size_t)e * st];
        int s = src_w[(size_t)e * st];
        int pos = atomicAdd(&g_cur[d], 1);
        g_esrc[g_off[d] + pos] = s;
    }

    // ---- exit: last arrival restores barrier counter for graph replay ----
    __syncthreads();
    if (tid == 0) {
        u32 v = atomicAdd(&g_barc, 1u);
        if (v == 6u * BUILD_BLOCKS - 1u)
            *((volatile u32*)&g_barc) = 0u;
    }
}

// ---------------------------------------------------------------------------
// K2: aggregate — one warp per node. Edge indices loaded COALESCED (one LDG
// serves 32 indices) then shfl-broadcast; row gathers in unrolled groups of
// 8 independent LDG.128 for MLP. fp32 accumulation.
// ---------------------------------------------------------------------------
__global__ void aggregate_kernel(const float* __restrict__ feat) {
    int warp = (blockIdx.x * blockDim.x + threadIdx.x) >> 5;
    int lane = threadIdx.x & 31;
    if (warp >= N_NODES) return;

    int start = g_off[warp];
    int cnt   = g_cnt[warp];

    float4 acc = make_float4(0.f, 0.f, 0.f, 0.f);

    for (int base = 0; base < cnt; base += 32) {
        int n = cnt - base; if (n > 32) n = 32;
        int myidx = (base + lane < cnt) ? g_esrc[start + base + lane] : 0;

        int j = 0;
        for (; j + 8 <= n; j += 8) {
            float4 v[8];
#pragma unroll
            for (int k = 0; k < 8; k++) {
                int s = __shfl_sync(0xFFFFFFFFu, myidx, j + k);
                v[k] = ((const float4*)(feat + (size_t)s * D))[lane];
            }
#pragma unroll
            for (int k = 0; k < 8; k++) {
                acc.x += v[k].x; acc.y += v[k].y;
                acc.z += v[k].z; acc.w += v[k].w;
            }
        }
        for (; j < n; j++) {
            int s = __shfl_sync(0xFFFFFFFFu, myidx, j);
            float4 v0 = ((const float4*)(feat + (size_t)s * D))[lane];
            acc.x += v0.x; acc.y += v0.y; acc.z += v0.z; acc.w += v0.w;
        }
    }

    float inv = 1.0f / (float)(cnt > 1 ? cnt : 1);
    acc.x *= inv; acc.y *= inv; acc.z *= inv; acc.w *= inv;
    g_hn4[(size_t)warp * (D / 4) + lane] = acc;
}

// ---------------------------------------------------------------------------
// K3: fused dual GEMM on tensor cores (tf32 mma.sync.m16n8k8):
//   out = [feat | h_neigh] @ [Ws ; Wn] + b     (virtual K = 256)
// ---------------------------------------------------------------------------
#define KC 32

__global__ __launch_bounds__(256)
void gemm_tf32_kernel(const float* __restrict__ feat,
                      const float* __restrict__ Ws,
                      const float* __restrict__ Wn,
                      const float* __restrict__ bias,
                      float* __restrict__ out) {
    __shared__ __align__(16) u32 A_s[128][36];
    __shared__ __align__(16) u32 B_s[KC][132];

    const int tid  = threadIdx.x;
    const int wid  = tid >> 5;
    const int lane = tid & 31;
    const int wm   = wid >> 2;
    const int wn   = wid & 3;
    const int gid  = lane >> 2;
    const int t4   = lane & 3;
    const int node0 = blockIdx.x * 128;
    const float* hng = (const float*)g_hn4;

    float d[4][4][4];
#pragma unroll
    for (int mt = 0; mt < 4; mt++)
#pragma unroll
        for (int nt = 0; nt < 4; nt++)
#pragma unroll
            for (int r = 0; r < 4; r++) d[mt][nt][r] = 0.f;

    for (int kc = 0; kc < 2 * D; kc += KC) {
        const float* Asrc = (kc < D) ? (feat + kc) : (hng + (kc - D));
        {
            int r  = tid >> 3;
            int c4 = (tid & 7) * 4;
#pragma unroll
            for (int rr = 0; rr < 128; rr += 32) {
                int gn = node0 + r + rr;
                float4 v = make_float4(0.f, 0.f, 0.f, 0.f);
                if (gn < N_NODES) v = *(const float4*)(Asrc + (size_t)gn * D + c4);
                uint4 u;
                u.x = f2tf32(v.x); u.y = f2tf32(v.y);
                u.z = f2tf32(v.z); u.w = f2tf32(v.w);
                *(uint4*)&A_s[r + rr][c4] = u;
            }
        }
        const float* Bsrc = (kc < D) ? (Ws + (size_t)kc * D)
                                     : (Wn + (size_t)(kc - D) * D);
#pragma unroll
        for (int j = 0; j < 4; j++) {
            int idx = tid + j * 256;
            int row = idx >> 5;
            int c4  = (idx & 31) * 4;
            float4 v = *(const float4*)(Bsrc + (size_t)row * D + c4);
            uint4 u;
            u.x = f2tf32(v.x); u.y = f2tf32(v.y);
            u.z = f2tf32(v.z); u.w = f2tf32(v.w);
            *(uint4*)&B_s[row][c4] = u;
        }
        __syncthreads();

#pragma unroll
        for (int kk = 0; kk < KC; kk += 8) {
            u32 bf[4][2];
#pragma unroll
            for (int nt = 0; nt < 4; nt++) {
                int col = wn * 32 + nt * 8 + gid;
                bf[nt][0] = B_s[kk + t4][col];
                bf[nt][1] = B_s[kk + t4 + 4][col];
            }
#pragma unroll
            for (int mt = 0; mt < 4; mt++) {
                int row = wm * 64 + mt * 16 + gid;
                u32 a0 = A_s[row][kk + t4];
                u32 a1 = A_s[row + 8][kk + t4];
                u32 a2 = A_s[row][kk + t4 + 4];
                u32 a3 = A_s[row + 8][kk + t4 + 4];
#pragma unroll
                for (int nt = 0; nt < 4; nt++) {
                    asm volatile(
                        "mma.sync.aligned.m16n8k8.row.col.f32.tf32.tf32.f32 "
                        "{%0,%1,%2,%3}, {%4,%5,%6,%7}, {%8,%9}, {%0,%1,%2,%3};"
                        : "+f"(d[mt][nt][0]), "+f"(d[mt][nt][1]),
                          "+f"(d[mt][nt][2]), "+f"(d[mt][nt][3])
                        : "r"(a0), "r"(a1), "r"(a2), "r"(a3),
                          "r"(bf[nt][0]), "r"(bf[nt][1]));
                }
            }
        }
        __syncthreads();
    }

#pragma unroll
    for (int nt = 0; nt < 4; nt++) {
        int col = wn * 32 + nt * 8 + 2 * t4;
        float2 bb = *(const float2*)(bias + col);
#pragma unroll
        for (int mt = 0; mt < 4; mt++) {
            int row = node0 + wm * 64 + mt * 16 + gid;
            if (row < N_NODES) {
                float2 o0; o0.x = d[mt][nt][0] + bb.x; o0.y = d[mt][nt][1] + bb.y;
                *(float2*)(out + (size_t)row * D + col) = o0;
            }
            if (row + 8 < N_NODES) {
                float2 o1; o1.x = d[mt][nt][2] + bb.x; o1.y = d[mt][nt][3] + bb.y;
                *(float2*)(out + (size_t)(row + 8) * D + col) = o1;
            }
        }
    }
}

// ---------------------------------------------------------------------------
// Launch: 3 kernels total
// ---------------------------------------------------------------------------
extern "C" void kernel_launch(void* const* d_in, const int* in_sizes, int n_in,
                              void* d_out, int out_size) {
    const float* feat  = (const float*)d_in[0];
    const int*   src_w = (const int*)d_in[1];
    const int*   dst_w = (const int*)d_in[2];
    const float* Ws    = (const float*)d_in[3];
    const float* Wn    = (const float*)d_in[4];
    const float* b     = (const float*)d_in[5];
    float*       out   = (float*)d_out;

    build_kernel<<<BUILD_BLOCKS, BUILD_THREADS>>>(src_w, dst_w);

    {   // aggregate: one warp per node
        int threads = 256;
        int blocks = (N_NODES * 32 + threads - 1) / threads;
        aggregate_kernel<<<blocks, threads>>>(feat);
    }

    {   // fused dual GEMM on tensor cores
        int blocks = (N_NODES + 127) / 128;
        gemm_tf32_kernel<<<blocks, 256>>>(feat, Ws, Wn, b, out);
    }
}

// round 12
// speedup vs baseline: 1.1346x; 1.1346x over previous
#include <cuda_runtime.h>
#include <cuda_bf16.h>
#include <cstdint>

#define N_NODES 50000
#define N_EDGES 800000
#define D 128

typedef unsigned int u32;

// ---------------------------------------------------------------------------
// Scratch (device globals: allocation-free per harness rules)
// ---------------------------------------------------------------------------
__device__ float4 g_hn4[(size_t)N_NODES * D / 4];  // h_neigh (mean), 25.6MB
__device__ int    g_cnt[N_NODES];                  // in-degree
__device__ int    g_off[N_NODES];                  // CSR offsets
__device__ int    g_rank[N_EDGES];                 // edge rank within dst bucket
__device__ int    g_esrc[N_EDGES];                 // src per edge, bucketed by dst
__device__ int    g_bsum[64];                      // scan block sums
__device__ int    g_stride;                        // 1 = int32 indices, 2 = int64

__device__ __forceinline__ u32 f2tf32(float f) {
    u32 r; asm("cvt.rna.tf32.f32 %0, %1;" : "=r"(r) : "f"(f)); return r;
}

// ---------------------------------------------------------------------------
// K0: zero counters + probe index dtype (block 0)
// ---------------------------------------------------------------------------
__global__ void zero_probe_kernel(const int* __restrict__ dst_w) {
    int i = blockIdx.x * blockDim.x + threadIdx.x;
    if (i < N_NODES) g_cnt[i] = 0;
    if (blockIdx.x == 0) {
        __shared__ int any_nonzero;
        if (threadIdx.x == 0) any_nonzero = 0;
        __syncthreads();
        int j = 1 + 2 * threadIdx.x;        // odd 32-bit words: all 0 iff int64
        if ((dst_w[j] | dst_w[j + 512]) != 0) atomicOr(&any_nonzero, 1);
        __syncthreads();
        if (threadIdx.x == 0) g_stride = any_nonzero ? 1 : 2;
    }
}

// ---------------------------------------------------------------------------
// K1: degree histogram; atomic return value = edge rank in its bucket
// (this is what lets the fill phase run atomic-free)
// ---------------------------------------------------------------------------
__global__ void count_kernel(const int* __restrict__ dst_w) {
    int e = blockIdx.x * blockDim.x + threadIdx.x;
    if (e >= N_EDGES) return;
    int d = dst_w[(size_t)e * g_stride];
    g_rank[e] = atomicAdd(&g_cnt[d], 1);
}

// ---------------------------------------------------------------------------
// K2a/b/c: parallel exclusive scan over 50K counts
// ---------------------------------------------------------------------------
#define SCAN_CHUNK 1024
#define SCAN_BLOCKS ((N_NODES + SCAN_CHUNK - 1) / SCAN_CHUNK)  // 49

__global__ void scan1_kernel() {               // per-block totals
    __shared__ int ssum[256];
    int b = blockIdx.x, t = threadIdx.x;
    int base = b * SCAN_CHUNK;
    int s = 0;
#pragma unroll
    for (int i = t; i < SCAN_CHUNK; i += 256) {
        int idx = base + i;
        if (idx < N_NODES) s += g_cnt[idx];
    }
    ssum[t] = s;
    __syncthreads();
    for (int o = 128; o > 0; o >>= 1) {
        if (t < o) ssum[t] += ssum[t + o];
        __syncthreads();
    }
    if (t == 0) g_bsum[b] = ssum[0];
}

__global__ void scan2_kernel() {               // exclusive scan of 49 sums, parallel
    __shared__ int sh[64];
    int t = threadIdx.x;
    int v = (t < SCAN_BLOCKS) ? g_bsum[t] : 0;
    sh[t] = v;
    __syncthreads();
    for (int o = 1; o < 64; o <<= 1) {
        int x = (t >= o) ? sh[t - o] : 0;
        __syncthreads();
        sh[t] += x;
        __syncthreads();
    }
    if (t < SCAN_BLOCKS) g_bsum[t] = sh[t] - v;  // exclusive
}

__global__ void scan3_kernel() {               // per-block exclusive scan + base
    __shared__ int tsum[256];
    int b = blockIdx.x, t = threadIdx.x;
    int idx0 = b * SCAN_CHUNK + t * 4;
    int v[4], s = 0;
#pragma unroll
    for (int j = 0; j < 4; j++) {
        int idx = idx0 + j;
        v[j] = (idx < N_NODES) ? g_cnt[idx] : 0;
        s += v[j];
    }
    tsum[t] = s;
    __syncthreads();
    for (int o = 1; o < 256; o <<= 1) {
        int x = (t >= o) ? tsum[t - o] : 0;
        __syncthreads();
        tsum[t] += x;
        __syncthreads();
    }
    int run = g_bsum[b] + (t > 0 ? tsum[t - 1] : 0);
#pragma unroll
    for (int j = 0; j < 4; j++) {
        int idx = idx0 + j;
        if (idx < N_NODES) g_off[idx] = run;
        run += v[j];
    }
}

// ---------------------------------------------------------------------------
// K3: bucket fill — NO atomics (rank precomputed in count phase)
// ---------------------------------------------------------------------------
__global__ void fill_kernel(const int* __restrict__ src_w,
                            const int* __restrict__ dst_w) {
    int e = blockIdx.x * blockDim.x + threadIdx.x;
    if (e >= N_EDGES) return;
    int st = g_stride;
    int d = dst_w[(size_t)e * st];
    int s = src_w[(size_t)e * st];
    g_esrc[g_off[d] + g_rank[e]] = s;
}

// ---------------------------------------------------------------------------
// K4: aggregate — one warp per node, per-edge broadcast index loads, x4
// unrolled independent LDG.128s (the measured-fastest variant; the shfl-
// broadcast restructure from R11 regressed and is reverted)
// ---------------------------------------------------------------------------
__global__ void aggregate_kernel(const float* __restrict__ feat) {
    int warp = (blockIdx.x * blockDim.x + threadIdx.x) >> 5;
    int lane = threadIdx.x & 31;
    if (warp >= N_NODES) return;

    int start = g_off[warp];
    int cnt   = g_cnt[warp];
    int end   = start + cnt;

    float4 acc = make_float4(0.f, 0.f, 0.f, 0.f);
    int e = start;
    for (; e + 4 <= end; e += 4) {
        int s0 = g_esrc[e + 0];
        int s1 = g_esrc[e + 1];
        int s2 = g_esrc[e + 2];
        int s3 = g_esrc[e + 3];
        float4 v0 = ((const float4*)(feat + (size_t)s0 * D))[lane];
        float4 v1 = ((const float4*)(feat + (size_t)s1 * D))[lane];
        float4 v2 = ((const float4*)(feat + (size_t)s2 * D))[lane];
        float4 v3 = ((const float4*)(feat + (size_t)s3 * D))[lane];
        acc.x += (v0.x + v1.x) + (v2.x + v3.x);
        acc.y += (v0.y + v1.y) + (v2.y + v3.y);
        acc.z += (v0.z + v1.z) + (v2.z + v3.z);
        acc.w += (v0.w + v1.w) + (v2.w + v3.w);
    }
    for (; e < end; e++) {
        int s0 = g_esrc[e];
        float4 v0 = ((const float4*)(feat + (size_t)s0 * D))[lane];
        acc.x += v0.x; acc.y += v0.y; acc.z += v0.z; acc.w += v0.w;
    }

    float inv = 1.0f / (float)(cnt > 1 ? cnt : 1);
    acc.x *= inv; acc.y *= inv; acc.z *= inv; acc.w *= inv;
    g_hn4[(size_t)warp * (D / 4) + lane] = acc;
}

// ---------------------------------------------------------------------------
// K5: fused dual GEMM on tensor cores (tf32 mma.sync.m16n8k8):
//   out = [feat | h_neigh] @ [Ws ; Wn] + b     (virtual K = 256)
// ---------------------------------------------------------------------------
#define KC 32

__global__ __launch_bounds__(256)
void gemm_tf32_kernel(const float* __restrict__ feat,
                      const float* __restrict__ Ws,
                      const float* __restrict__ Wn,
                      const float* __restrict__ bias,
                      float* __restrict__ out) {
    __shared__ __align__(16) u32 A_s[128][36];
    __shared__ __align__(16) u32 B_s[KC][132];

    const int tid  = threadIdx.x;
    const int wid  = tid >> 5;
    const int lane = tid & 31;
    const int wm   = wid >> 2;
    const int wn   = wid & 3;
    const int gid  = lane >> 2;
    const int t4   = lane & 3;
    const int node0 = blockIdx.x * 128;
    const float* hng = (const float*)g_hn4;

    float d[4][4][4];
#pragma unroll
    for (int mt = 0; mt < 4; mt++)
#pragma unroll
        for (int nt = 0; nt < 4; nt++)
#pragma unroll
            for (int r = 0; r < 4; r++) d[mt][nt][r] = 0.f;

    for (int kc = 0; kc < 2 * D; kc += KC) {
        const float* Asrc = (kc < D) ? (feat + kc) : (hng + (kc - D));
        {
            int r  = tid >> 3;
            int c4 = (tid & 7) * 4;
#pragma unroll
            for (int rr = 0; rr < 128; rr += 32) {
                int gn = node0 + r + rr;
                float4 v = make_float4(0.f, 0.f, 0.f, 0.f);
                if (gn < N_NODES) v = *(const float4*)(Asrc + (size_t)gn * D + c4);
                uint4 u;
                u.x = f2tf32(v.x); u.y = f2tf32(v.y);
                u.z = f2tf32(v.z); u.w = f2tf32(v.w);
                *(uint4*)&A_s[r + rr][c4] = u;
            }
        }
        const float* Bsrc = (kc < D) ? (Ws + (size_t)kc * D)
                                     : (Wn + (size_t)(kc - D) * D);
#pragma unroll
        for (int j = 0; j < 4; j++) {
            int idx = tid + j * 256;
            int row = idx >> 5;
            int c4  = (idx & 31) * 4;
            float4 v = *(const float4*)(Bsrc + (size_t)row * D + c4);
            uint4 u;
            u.x = f2tf32(v.x); u.y = f2tf32(v.y);
            u.z = f2tf32(v.z); u.w = f2tf32(v.w);
            *(uint4*)&B_s[row][c4] = u;
        }
        __syncthreads();

#pragma unroll
        for (int kk = 0; kk < KC; kk += 8) {
            u32 bf[4][2];
#pragma unroll
            for (int nt = 0; nt < 4; nt++) {
                int col = wn * 32 + nt * 8 + gid;
                bf[nt][0] = B_s[kk + t4][col];
                bf[nt][1] = B_s[kk + t4 + 4][col];
            }
#pragma unroll
            for (int mt = 0; mt < 4; mt++) {
                int row = wm * 64 + mt * 16 + gid;
                u32 a0 = A_s[row][kk + t4];
                u32 a1 = A_s[row + 8][kk + t4];
                u32 a2 = A_s[row][kk + t4 + 4];
                u32 a3 = A_s[row + 8][kk + t4 + 4];
#pragma unroll
                for (int nt = 0; nt < 4; nt++) {
                    asm volatile(
                        "mma.sync.aligned.m16n8k8.row.col.f32.tf32.tf32.f32 "
                        "{%0,%1,%2,%3}, {%4,%5,%6,%7}, {%8,%9}, {%0,%1,%2,%3};"
                        : "+f"(d[mt][nt][0]), "+f"(d[mt][nt][1]),
                          "+f"(d[mt][nt][2]), "+f"(d[mt][nt][3])
                        : "r"(a0), "r"(a1), "r"(a2), "r"(a3),
                          "r"(bf[nt][0]), "r"(bf[nt][1]));
                }
            }
        }
        __syncthreads();
    }

#pragma unroll
    for (int nt = 0; nt < 4; nt++) {
        int col = wn * 32 + nt * 8 + 2 * t4;
        float2 bb = *(const float2*)(bias + col);
#pragma unroll
        for (int mt = 0; mt < 4; mt++) {
            int row = node0 + wm * 64 + mt * 16 + gid;
            if (row < N_NODES) {
                float2 o0; o0.x = d[mt][nt][0] + bb.x; o0.y = d[mt][nt][1] + bb.y;
                *(float2*)(out + (size_t)row * D + col) = o0;
            }
            if (row + 8 < N_NODES) {
                float2 o1; o1.x = d[mt][nt][2] + bb.x; o1.y = d[mt][nt][3] + bb.y;
                *(float2*)(out + (size_t)(row + 8) * D + col) = o1;
            }
        }
    }
}

// ---------------------------------------------------------------------------
// Launch
// ---------------------------------------------------------------------------
extern "C" void kernel_launch(void* const* d_in, const int* in_sizes, int n_in,
                              void* d_out, int out_size) {
    const float* feat  = (const float*)d_in[0];
    const int*   src_w = (const int*)d_in[1];
    const int*   dst_w = (const int*)d_in[2];
    const float* Ws    = (const float*)d_in[3];
    const float* Wn    = (const float*)d_in[4];
    const float* b     = (const float*)d_in[5];
    float*       out   = (float*)d_out;

    zero_probe_kernel<<<(N_NODES + 255) / 256, 256>>>(dst_w);
    count_kernel<<<(N_EDGES + 255) / 256, 256>>>(dst_w);
    scan1_kernel<<<SCAN_BLOCKS, 256>>>();
    scan2_kernel<<<1, 64>>>();
    scan3_kernel<<<SCAN_BLOCKS, 256>>>();
    fill_kernel<<<(N_EDGES + 255) / 256, 256>>>(src_w, dst_w);

    {   // aggregate: one warp per node
        int threads = 256;
        int blocks = (N_NODES * 32 + threads - 1) / threads;
        aggregate_kernel<<<blocks, threads>>>(feat);
    }

    {   // fused dual GEMM on tensor cores
        int blocks = (N_NODES + 127) / 128;
        gemm_tf32_kernel<<<blocks, 256>>>(feat, Ws, Wn, b, out);
    }
}